// round 4
// baseline (speedup 1.0000x reference)
#include <cuda_runtime.h>

// SAKE GNN fully fused, one CTA per graph (B=512, M=32, H=128, L=2).
// R4: 512 threads (16 warps) for latency hiding; pair-GEMM A operand stored
//     pre-duplicated (f32x2) in shared so the hot loop is LDS.128 + FFMA2 only.

#define NB 512
#define NT 512
typedef unsigned long long u64;

// ---- shared memory layout (float offsets) ----
#define S_HG    0        // 32x128
#define S_MI    4096
#define S_MJ    8192
#define S_AGG   12288
#define S_W     16384    // 128x128 weight staging
#define S_M1    32768    // 16 warps x 4 rows x 128 u64 (duplicated) = 16384 floats
#define S_D2    49152    // 32x32
#define S_EDGE  50176    // 1024 ints
#define S_RMASK 51200
#define S_ROFF  51232
#define S_X     51264    // 96
#define S_HT    51360    // 32x16
#define S_RED   51872    // 16
#define S_NE    51888
#define SM_FLOATS 51892

__device__ __forceinline__ float silu_f(float v) {
    return __fdividef(v, 1.0f + __expf(-v));
}
__device__ __forceinline__ u64 pk2(float x) {
    u64 r; asm("mov.b64 %0, {%1, %1};" : "=l"(r) : "f"(x)); return r;
}
__device__ __forceinline__ void ffma2(u64& d, u64 a, u64 b) {
    asm("fma.rn.f32x2 %0, %1, %2, %0;" : "+l"(d) : "l"(a), "l"(b));
}
__device__ __forceinline__ float2 unpk(u64 v) {
    float2 f; asm("mov.b64 {%0, %1}, %2;" : "=f"(f.x), "=f"(f.y) : "l"(v)); return f;
}
__device__ __forceinline__ float4 acc4(u64 p0, u64 p1) {
    float2 a = unpk(p0), b = unpk(p1);
    float4 r = { a.x, a.y, b.x, b.y };
    return r;
}

__device__ __forceinline__ void cp16(unsigned saddr, const float* g) {
    asm volatile("cp.async.cg.shared.global [%0], [%1], 16;" :: "r"(saddr), "l"(g));
}
#define CP_COMMIT() asm volatile("cp.async.commit_group;")
#define CP_WAIT0()  asm volatile("cp.async.wait_group 0;" ::: "memory")

__device__ __forceinline__ void stage_async(const float* __restrict__ g,
                                            float* s, int nf4) {
    unsigned sa = (unsigned)__cvta_generic_to_shared(s);
    for (int v = threadIdx.x; v < nf4; v += NT)
        cp16(sa + v * 16, g + v * 4);
}

// node GEMM: R rows per warp; acc[rr][p] (f32x2) over cols k0+2p+{0,1}
template <int R>
__device__ __forceinline__ void gemmN(const float* __restrict__ sX, int ldx,
                                      const float* __restrict__ sW, int nh,
                                      int i0, int k0, u64 acc[R][2]) {
    #pragma unroll 1
    for (int h = 0; h < nh; h += 4) {
        ulonglong2 w0 = *(const ulonglong2*)&sW[(h + 0) * 128 + k0];
        ulonglong2 w1 = *(const ulonglong2*)&sW[(h + 1) * 128 + k0];
        ulonglong2 w2 = *(const ulonglong2*)&sW[(h + 2) * 128 + k0];
        ulonglong2 w3 = *(const ulonglong2*)&sW[(h + 3) * 128 + k0];
        #pragma unroll
        for (int rr = 0; rr < R; rr++) {
            float4 a = *(const float4*)&sX[(i0 + rr) * ldx + h];
            u64 a0 = pk2(a.x), a1 = pk2(a.y), a2 = pk2(a.z), a3 = pk2(a.w);
            ffma2(acc[rr][0], a0, w0.x); ffma2(acc[rr][1], a0, w0.y);
            ffma2(acc[rr][0], a1, w1.x); ffma2(acc[rr][1], a1, w1.y);
            ffma2(acc[rr][0], a2, w2.x); ffma2(acc[rr][1], a2, w2.y);
            ffma2(acc[rr][0], a3, w3.x); ffma2(acc[rr][1], a3, w3.y);
        }
    }
}

// edge GEMM: A pre-duplicated (u64 per h), 4 rows; no MOVs in the loop
__device__ __forceinline__ void gemmE(const u64* __restrict__ aD,
                                      const float* __restrict__ sW,
                                      int k0, u64 y[4][2]) {
    #pragma unroll 1
    for (int h = 0; h < 128; h += 4) {
        ulonglong2 w0 = *(const ulonglong2*)&sW[(h + 0) * 128 + k0];
        ulonglong2 w1 = *(const ulonglong2*)&sW[(h + 1) * 128 + k0];
        ulonglong2 w2 = *(const ulonglong2*)&sW[(h + 2) * 128 + k0];
        ulonglong2 w3 = *(const ulonglong2*)&sW[(h + 3) * 128 + k0];
        #pragma unroll
        for (int rr = 0; rr < 4; rr++) {
            ulonglong2 p0 = *(const ulonglong2*)&aD[rr * 128 + h];
            ulonglong2 p1 = *(const ulonglong2*)&aD[rr * 128 + h + 2];
            ffma2(y[rr][0], p0.x, w0.x); ffma2(y[rr][1], p0.x, w0.y);
            ffma2(y[rr][0], p0.y, w1.x); ffma2(y[rr][1], p0.y, w1.y);
            ffma2(y[rr][0], p1.x, w2.x); ffma2(y[rr][1], p1.x, w2.y);
            ffma2(y[rr][0], p1.y, w3.x); ffma2(y[rr][1], p1.y, w3.y);
        }
    }
}

__global__ void __launch_bounds__(NT, 1)
sake_kernel(const float* __restrict__ g_h, const float* __restrict__ g_x,
            const float* __restrict__ W_in, const float* __restrict__ b_in,
            const float* __restrict__ We1, const float* __restrict__ be1,
            const float* __restrict__ We2, const float* __restrict__ be2,
            const float* __restrict__ Wh1, const float* __restrict__ bh1,
            const float* __restrict__ Wh2, const float* __restrict__ bh2,
            const float* __restrict__ W_out, const float* __restrict__ b_out,
            const float* __restrict__ Wn1, const float* __restrict__ bn1,
            const float* __restrict__ Wn2, const float* __restrict__ bn2,
            float* __restrict__ g_out)
{
    extern __shared__ float sm[];
    float*    s_hg  = sm + S_HG;
    float*    s_mi  = sm + S_MI;
    float*    s_mj  = sm + S_MJ;
    float*    s_agg = sm + S_AGG;
    float*    s_W   = sm + S_W;
    float*    s_d2  = sm + S_D2;
    int*      s_edge  = (int*)(sm + S_EDGE);
    unsigned* s_rmask = (unsigned*)(sm + S_RMASK);
    int*      s_roff  = (int*)(sm + S_ROFF);
    float*    s_x   = sm + S_X;
    float*    s_ht  = sm + S_HT;
    float*    s_red = sm + S_RED;
    int*      s_ne  = (int*)(sm + S_NE);

    const int tid  = threadIdx.x;
    const int warp = tid >> 5;      // 0..15
    const int lane = tid & 31;
    const int b    = blockIdx.x;
    const int i0   = warp * 2;      // node-GEMM row base (2 rows/warp)
    const int k0   = lane * 4;

    // ---- prologue: stage x, h, W_in ----
    {
        unsigned sx = (unsigned)__cvta_generic_to_shared(s_x);
        if (tid < 24) cp16(sx + tid * 16, g_x + b * 96 + tid * 4);
        unsigned sh = (unsigned)__cvta_generic_to_shared(s_ht);
        if (tid < 128) cp16(sh + tid * 16, g_h + b * 512 + tid * 4);
        stage_async(W_in, s_W, 512);
        CP_COMMIT(); CP_WAIT0();
    }
    __syncthreads();

    // ---- d2 ----
    for (int p = tid; p < 1024; p += NT) {
        int i = p >> 5, j = p & 31;
        float dx = s_x[i * 3 + 0] - s_x[j * 3 + 0];
        float dy = s_x[i * 3 + 1] - s_x[j * 3 + 1];
        float dz = s_x[i * 3 + 2] - s_x[j * 3 + 2];
        s_d2[p] = dx * dx + dy * dy + dz * dz;
    }
    __syncthreads();

    // ---- adjacency masks + hg = h @ W_in + b_in ----
    #pragma unroll
    for (int rr = 0; rr < 2; rr++) {
        int i = i0 + rr;
        bool adj = (s_d2[i * 32 + lane] < 1.0f) && (lane != i);
        unsigned m = __ballot_sync(0xffffffffu, adj);
        if (lane == 0) s_rmask[i] = m;
    }
    {
        u64 acc[2][2] = {};
        gemmN<2>(s_ht, 16, s_W, 16, i0, k0, acc);
        float4 bb = *(const float4*)&b_in[k0];
        #pragma unroll
        for (int rr = 0; rr < 2; rr++) {
            float4 o = acc4(acc[rr][0], acc[rr][1]);
            o.x += bb.x; o.y += bb.y; o.z += bb.z; o.w += bb.w;
            *(float4*)&s_hg[(i0 + rr) * 128 + k0] = o;
        }
    }
    __syncthreads();

    // ---- edge-list scan (layer-invariant, sorted by i) ----
    if (warp == 0) {
        unsigned m = s_rmask[lane];
        int c = __popc(m);
        int inc = c;
        #pragma unroll
        for (int d = 1; d < 32; d <<= 1) {
            int n = __shfl_up_sync(0xffffffffu, inc, d);
            if (lane >= d) inc += n;
        }
        s_roff[lane] = inc - c;
        if (lane == 31) *s_ne = inc;
    }
    __syncthreads();
    #pragma unroll
    for (int rr = 0; rr < 2; rr++) {
        int i = i0 + rr;
        unsigned m = s_rmask[i];
        if ((m >> lane) & 1u) {
            int pos = s_roff[i] + __popc(m & ((1u << lane) - 1u));
            s_edge[pos] = (i << 5) | lane;
        }
    }
    __syncthreads();
    const int nE = *s_ne;
    const int nper = (nE + 15) >> 4;

    // ---- layers ----
    #pragma unroll 1
    for (int l = 0; l < 2; l++) {
        const float* We1l = We1 + l * (257 * 128);
        const float* We2l = We2 + l * 16384;
        const float* Wh1l = Wh1 + l * (256 * 128);
        const float* Wh2l = Wh2 + l * 16384;

        // mi = hg @ We1a + be1
        stage_async(We1l, s_W, 4096); CP_COMMIT(); CP_WAIT0();
        __syncthreads();
        {
            u64 acc[2][2] = {};
            gemmN<2>(s_hg, 128, s_W, 128, i0, k0, acc);
            float4 bb = *(const float4*)&be1[l * 128 + k0];
            #pragma unroll
            for (int rr = 0; rr < 2; rr++) {
                float4 o = acc4(acc[rr][0], acc[rr][1]);
                o.x += bb.x; o.y += bb.y; o.z += bb.z; o.w += bb.w;
                *(float4*)&s_mi[(i0 + rr) * 128 + k0] = o;
            }
        }
        __syncthreads();

        // mj = hg @ We1b
        stage_async(We1l + 16384, s_W, 4096); CP_COMMIT(); CP_WAIT0();
        __syncthreads();
        {
            u64 acc[2][2] = {};
            gemmN<2>(s_hg, 128, s_W, 128, i0, k0, acc);
            #pragma unroll
            for (int rr = 0; rr < 2; rr++)
                *(float4*)&s_mj[(i0 + rr) * 128 + k0] = acc4(acc[rr][0], acc[rr][1]);
        }
        __syncthreads();

        // stage We2; zero agg
        stage_async(We2l, s_W, 4096); CP_COMMIT();
        for (int v = tid; v < 4096; v += NT) s_agg[v] = 0.0f;
        CP_WAIT0();
        __syncthreads();

        // ---- balanced pair phase: 16 contiguous edge slices ----
        {
            const float4 wdv  = *(const float4*)&We1l[256 * 128 + k0];
            const float4 be2v = *(const float4*)&be2[l * 128 + k0];
            u64* m1d = (u64*)(sm + S_M1) + warp * 512;   // 4 rows x 128 u64
            const int e_lo = min(warp * nper, nE);
            const int e_hi = min(e_lo + nper, nE);

            int   cur_i = -1;
            float a0 = 0.f, a1 = 0.f, a2 = 0.f, a3 = 0.f;

            for (int e0 = e_lo; e0 < e_hi; e0 += 4) {
                // build up to 4 dup'd rows: m1 = silu(mi[i] + mj[j] + d2*wd + be1)
                #pragma unroll
                for (int rr = 0; rr < 4; rr++) {
                    int e = e0 + rr;
                    int ij = s_edge[e < e_hi ? e : (e_hi - 1)];
                    int i = ij >> 5, j = ij & 31;
                    float dd = s_d2[ij];
                    float4 miv = *(const float4*)&s_mi[i * 128 + k0];
                    float4 mjv = *(const float4*)&s_mj[j * 128 + k0];
                    u64 d0 = pk2(silu_f(miv.x + mjv.x + dd * wdv.x));
                    u64 d1 = pk2(silu_f(miv.y + mjv.y + dd * wdv.y));
                    u64 d2v = pk2(silu_f(miv.z + mjv.z + dd * wdv.z));
                    u64 d3 = pk2(silu_f(miv.w + mjv.w + dd * wdv.w));
                    ulonglong2* p = (ulonglong2*)&m1d[rr * 128 + k0];
                    p[0] = make_ulonglong2(d0, d1);
                    p[1] = make_ulonglong2(d2v, d3);
                }
                __syncwarp();
                u64 y[4][2] = {};
                gemmE(m1d, s_W, k0, y);
                __syncwarp();   // protect m1d before next chunk overwrites

                #pragma unroll
                for (int rr = 0; rr < 4; rr++) {
                    int e = e0 + rr;
                    if (e < e_hi) {
                        int i = s_edge[e] >> 5;   // uniform across warp
                        float4 o = acc4(y[rr][0], y[rr][1]);
                        float v0 = silu_f(o.x + be2v.x);
                        float v1 = silu_f(o.y + be2v.y);
                        float v2 = silu_f(o.z + be2v.z);
                        float v3 = silu_f(o.w + be2v.w);
                        if (i != cur_i) {
                            if (cur_i >= 0) {
                                float* ag = &s_agg[cur_i * 128 + k0];
                                atomicAdd(ag + 0, a0); atomicAdd(ag + 1, a1);
                                atomicAdd(ag + 2, a2); atomicAdd(ag + 3, a3);
                            }
                            cur_i = i;
                            a0 = v0; a1 = v1; a2 = v2; a3 = v3;
                        } else {
                            a0 += v0; a1 += v1; a2 += v2; a3 += v3;
                        }
                    }
                }
            }
            if (cur_i >= 0) {
                float* ag = &s_agg[cur_i * 128 + k0];
                atomicAdd(ag + 0, a0); atomicAdd(ag + 1, a1);
                atomicAdd(ag + 2, a2); atomicAdd(ag + 3, a3);
            }
        }
        __syncthreads();

        // u = silu(hg @ Wh1a + agg @ Wh1b + bh1) -> s_mi
        stage_async(Wh1l, s_W, 4096); CP_COMMIT(); CP_WAIT0();
        __syncthreads();
        u64 acc[2][2] = {};
        gemmN<2>(s_hg, 128, s_W, 128, i0, k0, acc);
        __syncthreads();
        stage_async(Wh1l + 16384, s_W, 4096); CP_COMMIT(); CP_WAIT0();
        __syncthreads();
        gemmN<2>(s_agg, 128, s_W, 128, i0, k0, acc);
        {
            float4 bb = *(const float4*)&bh1[l * 128 + k0];
            #pragma unroll
            for (int rr = 0; rr < 2; rr++) {
                float4 o = acc4(acc[rr][0], acc[rr][1]);
                float4 u4 = { silu_f(o.x + bb.x), silu_f(o.y + bb.y),
                              silu_f(o.z + bb.z), silu_f(o.w + bb.w) };
                *(float4*)&s_mi[(i0 + rr) * 128 + k0] = u4;
            }
        }
        __syncthreads();

        // hg += u @ Wh2 + bh2
        stage_async(Wh2l, s_W, 4096); CP_COMMIT(); CP_WAIT0();
        __syncthreads();
        {
            u64 acc2[2][2] = {};
            gemmN<2>(s_mi, 128, s_W, 128, i0, k0, acc2);
            float4 bb = *(const float4*)&bh2[l * 128 + k0];
            #pragma unroll
            for (int rr = 0; rr < 2; rr++) {
                float4 o = acc4(acc2[rr][0], acc2[rr][1]);
                float4 cur = *(float4*)&s_hg[(i0 + rr) * 128 + k0];
                cur.x += o.x + bb.x; cur.y += o.y + bb.y;
                cur.z += o.z + bb.z; cur.w += o.w + bb.w;
                *(float4*)&s_hg[(i0 + rr) * 128 + k0] = cur;
            }
        }
        __syncthreads();
    }

    // ---- head: ho = hg @ W_out + b_out -> s_mj ----
    stage_async(W_out, s_W, 4096); CP_COMMIT(); CP_WAIT0();
    __syncthreads();
    {
        u64 acc[2][2] = {};
        gemmN<2>(s_hg, 128, s_W, 128, i0, k0, acc);
        float4 bb = *(const float4*)&b_out[k0];
        #pragma unroll
        for (int rr = 0; rr < 2; rr++) {
            float4 o = acc4(acc[rr][0], acc[rr][1]);
            o.x += bb.x; o.y += bb.y; o.z += bb.z; o.w += bb.w;
            *(float4*)&s_mj[(i0 + rr) * 128 + k0] = o;
        }
    }
    __syncthreads();

    // t1 = silu(ho @ Wn1 + bn1) -> s_mi
    stage_async(Wn1, s_W, 4096); CP_COMMIT(); CP_WAIT0();
    __syncthreads();
    {
        u64 acc[2][2] = {};
        gemmN<2>(s_mj, 128, s_W, 128, i0, k0, acc);
        float4 bb = *(const float4*)&bn1[k0];
        #pragma unroll
        for (int rr = 0; rr < 2; rr++) {
            float4 o = acc4(acc[rr][0], acc[rr][1]);
            float4 t = { silu_f(o.x + bb.x), silu_f(o.y + bb.y),
                         silu_f(o.z + bb.z), silu_f(o.w + bb.w) };
            *(float4*)&s_mi[(i0 + rr) * 128 + k0] = t;
        }
    }
    __syncthreads();

    // ---- out[b] = (colsum t1) . Wn2 + 32*bn2 ----
    float part = 0.0f;
    if (tid < 128) {
        float s = 0.0f;
        #pragma unroll
        for (int i = 0; i < 32; i++) s += s_mi[i * 128 + tid];
        part = s * Wn2[tid];
    }
    #pragma unroll
    for (int off = 16; off > 0; off >>= 1)
        part += __shfl_down_sync(0xffffffffu, part, off);
    if (warp < 4 && lane == 0) s_red[warp] = part;
    __syncthreads();
    if (tid == 0)
        g_out[b] = s_red[0] + s_red[1] + s_red[2] + s_red[3] + 32.0f * bn2[0];
}

extern "C" void kernel_launch(void* const* d_in, const int* in_sizes, int n_in,
                              void* d_out, int out_size) {
    const float* g_h   = (const float*)d_in[0];
    const float* g_x   = (const float*)d_in[1];
    const float* W_in  = (const float*)d_in[3];
    const float* b_in  = (const float*)d_in[4];
    const float* We1   = (const float*)d_in[5];
    const float* be1   = (const float*)d_in[6];
    const float* We2   = (const float*)d_in[7];
    const float* be2   = (const float*)d_in[8];
    const float* Wh1   = (const float*)d_in[9];
    const float* bh1   = (const float*)d_in[10];
    const float* Wh2   = (const float*)d_in[11];
    const float* bh2   = (const float*)d_in[12];
    const float* W_out = (const float*)d_in[13];
    const float* b_out = (const float*)d_in[14];
    const float* Wn1   = (const float*)d_in[15];
    const float* bn1   = (const float*)d_in[16];
    const float* Wn2   = (const float*)d_in[17];
    const float* bn2   = (const float*)d_in[18];
    float* out = (float*)d_out;

    const int smem_bytes = SM_FLOATS * 4;
    cudaFuncSetAttribute(sake_kernel, cudaFuncAttributeMaxDynamicSharedMemorySize,
                         smem_bytes);
    sake_kernel<<<NB, NT, smem_bytes>>>(
        g_h, g_x, W_in, b_in, We1, be1, We2, be2, Wh1, bh1, Wh2, bh2,
        W_out, b_out, Wn1, bn1, Wn2, bn2, out);
}

// round 5
// speedup vs baseline: 1.1407x; 1.1407x over previous
#include <cuda_runtime.h>

// SAKE GNN fully fused, one CTA per graph (B=512, M=32, H=128, L=2).
// R5: back to 256 thr / 8 warps (R3 config); software-pipelined (double-
//     buffered) inner GEMM loops; edge A pre-duplicated as f32x2 in smem.

#define NB 512
#define NT 256
typedef unsigned long long u64;

// ---- shared memory layout (float offsets) ----
#define S_HG    0        // 32x128
#define S_MI    4096
#define S_MJ    8192
#define S_AGG   12288
#define S_W     16384    // 128x128 weight staging
#define S_M1    32768    // 8 warps x 4 rows x 128 u64 = 8192 floats
#define S_D2    40960    // 32x32
#define S_EDGE  41984    // 1024 ints
#define S_RMASK 43008
#define S_ROFF  43040
#define S_X     43072    // 96
#define S_HT    43168    // 32x16
#define S_RED   43680
#define S_NE    43688
#define SM_FLOATS 43696

__device__ __forceinline__ float silu_f(float v) {
    return __fdividef(v, 1.0f + __expf(-v));
}
__device__ __forceinline__ u64 pk2(float x) {
    u64 r; asm("mov.b64 %0, {%1, %1};" : "=l"(r) : "f"(x)); return r;
}
__device__ __forceinline__ void ffma2(u64& d, u64 a, u64 b) {
    asm("fma.rn.f32x2 %0, %1, %2, %0;" : "+l"(d) : "l"(a), "l"(b));
}
__device__ __forceinline__ float2 unpk(u64 v) {
    float2 f; asm("mov.b64 {%0, %1}, %2;" : "=f"(f.x), "=f"(f.y) : "l"(v)); return f;
}
__device__ __forceinline__ float4 acc4(u64 p0, u64 p1) {
    float2 a = unpk(p0), b = unpk(p1);
    float4 r = { a.x, a.y, b.x, b.y };
    return r;
}

__device__ __forceinline__ void cp16(unsigned saddr, const float* g) {
    asm volatile("cp.async.cg.shared.global [%0], [%1], 16;" :: "r"(saddr), "l"(g));
}
#define CP_COMMIT() asm volatile("cp.async.commit_group;")
#define CP_WAIT0()  asm volatile("cp.async.wait_group 0;" ::: "memory")

__device__ __forceinline__ void stage_async(const float* __restrict__ g,
                                            float* s, int nf4) {
    unsigned sa = (unsigned)__cvta_generic_to_shared(s);
    for (int v = threadIdx.x; v < nf4; v += NT)
        cp16(sa + v * 16, g + v * 4);
}

// ---- pipelined GEMM building blocks ----
struct W4 { ulonglong2 a, b, c, d; };

__device__ __forceinline__ W4 ldW(const float* __restrict__ sW, int h, int k0) {
    W4 w;
    w.a = *(const ulonglong2*)&sW[(h + 0) * 128 + k0];
    w.b = *(const ulonglong2*)&sW[(h + 1) * 128 + k0];
    w.c = *(const ulonglong2*)&sW[(h + 2) * 128 + k0];
    w.d = *(const ulonglong2*)&sW[(h + 3) * 128 + k0];
    return w;
}

__device__ __forceinline__ void ldA(const float* __restrict__ sX, int ldx,
                                    int i0, int h, float4 a[4]) {
    #pragma unroll
    for (int rr = 0; rr < 4; rr++) a[rr] = *(const float4*)&sX[(i0 + rr) * ldx + h];
}

__device__ __forceinline__ void fmaN(const float4 a[4], const W4& w, u64 acc[4][2]) {
    #pragma unroll
    for (int rr = 0; rr < 4; rr++) {
        u64 x0 = pk2(a[rr].x), x1 = pk2(a[rr].y), x2 = pk2(a[rr].z), x3 = pk2(a[rr].w);
        ffma2(acc[rr][0], x0, w.a.x); ffma2(acc[rr][1], x0, w.a.y);
        ffma2(acc[rr][0], x1, w.b.x); ffma2(acc[rr][1], x1, w.b.y);
        ffma2(acc[rr][0], x2, w.c.x); ffma2(acc[rr][1], x2, w.c.y);
        ffma2(acc[rr][0], x3, w.d.x); ffma2(acc[rr][1], x3, w.d.y);
    }
}

// node GEMM, nh=128, 4 rows/warp, double-buffered W+A prefetch
__device__ __forceinline__ void gemmP(const float* __restrict__ sX, int ldx,
                                      const float* __restrict__ sW,
                                      int i0, int k0, u64 acc[4][2]) {
    float4 aA[4], aB[4];
    W4 wA, wB;
    wA = ldW(sW, 0, k0);
    ldA(sX, ldx, i0, 0, aA);
    #pragma unroll 1
    for (int h = 0; h < 128; h += 8) {
        wB = ldW(sW, h + 4, k0);
        ldA(sX, ldx, i0, h + 4, aB);
        fmaN(aA, wA, acc);
        int hn = (h + 8) & 127;
        wA = ldW(sW, hn, k0);
        ldA(sX, ldx, i0, hn, aA);
        fmaN(aB, wB, acc);
    }
}

// edge GEMM: A pre-duplicated u64 rows, broadcast reads, pipelined
struct A4E { ulonglong2 p, q; };

__device__ __forceinline__ void ldAE(const u64* __restrict__ aD, int h, A4E a[4]) {
    #pragma unroll
    for (int rr = 0; rr < 4; rr++) {
        a[rr].p = *(const ulonglong2*)&aD[rr * 128 + h];
        a[rr].q = *(const ulonglong2*)&aD[rr * 128 + h + 2];
    }
}

__device__ __forceinline__ void fmaE(const A4E a[4], const W4& w, u64 acc[4][2]) {
    #pragma unroll
    for (int rr = 0; rr < 4; rr++) {
        ffma2(acc[rr][0], a[rr].p.x, w.a.x); ffma2(acc[rr][1], a[rr].p.x, w.a.y);
        ffma2(acc[rr][0], a[rr].p.y, w.b.x); ffma2(acc[rr][1], a[rr].p.y, w.b.y);
        ffma2(acc[rr][0], a[rr].q.x, w.c.x); ffma2(acc[rr][1], a[rr].q.x, w.c.y);
        ffma2(acc[rr][0], a[rr].q.y, w.d.x); ffma2(acc[rr][1], a[rr].q.y, w.d.y);
    }
}

__device__ __forceinline__ void gemmPE(const u64* __restrict__ aD,
                                       const float* __restrict__ sW,
                                       int k0, u64 acc[4][2]) {
    A4E aA[4], aB[4];
    W4 wA, wB;
    wA = ldW(sW, 0, k0);
    ldAE(aD, 0, aA);
    #pragma unroll 1
    for (int h = 0; h < 128; h += 8) {
        wB = ldW(sW, h + 4, k0);
        ldAE(aD, h + 4, aB);
        fmaE(aA, wA, acc);
        int hn = (h + 8) & 127;
        wA = ldW(sW, hn, k0);
        ldAE(aD, hn, aA);
        fmaE(aB, wB, acc);
    }
}

// small GEMM for the W_in phase (nh = 16)
__device__ __forceinline__ void gemmS(const float* __restrict__ sX,
                                      const float* __restrict__ sW,
                                      int i0, int k0, u64 acc[4][2]) {
    #pragma unroll
    for (int h = 0; h < 16; h += 4) {
        W4 w = ldW(sW, h, k0);
        float4 a[4];
        ldA(sX, 16, i0, h, a);
        fmaN(a, w, acc);
    }
}

__global__ void __launch_bounds__(NT, 1)
sake_kernel(const float* __restrict__ g_h, const float* __restrict__ g_x,
            const float* __restrict__ W_in, const float* __restrict__ b_in,
            const float* __restrict__ We1, const float* __restrict__ be1,
            const float* __restrict__ We2, const float* __restrict__ be2,
            const float* __restrict__ Wh1, const float* __restrict__ bh1,
            const float* __restrict__ Wh2, const float* __restrict__ bh2,
            const float* __restrict__ W_out, const float* __restrict__ b_out,
            const float* __restrict__ Wn1, const float* __restrict__ bn1,
            const float* __restrict__ Wn2, const float* __restrict__ bn2,
            float* __restrict__ g_out)
{
    extern __shared__ float sm[];
    float*    s_hg  = sm + S_HG;
    float*    s_mi  = sm + S_MI;
    float*    s_mj  = sm + S_MJ;
    float*    s_agg = sm + S_AGG;
    float*    s_W   = sm + S_W;
    float*    s_d2  = sm + S_D2;
    int*      s_edge  = (int*)(sm + S_EDGE);
    unsigned* s_rmask = (unsigned*)(sm + S_RMASK);
    int*      s_roff  = (int*)(sm + S_ROFF);
    float*    s_x   = sm + S_X;
    float*    s_ht  = sm + S_HT;
    float*    s_red = sm + S_RED;
    int*      s_ne  = (int*)(sm + S_NE);

    const int tid  = threadIdx.x;
    const int warp = tid >> 5;      // 0..7
    const int lane = tid & 31;
    const int b    = blockIdx.x;
    const int i0   = warp * 4;
    const int k0   = lane * 4;

    // ---- prologue: stage x, h, W_in ----
    {
        unsigned sx = (unsigned)__cvta_generic_to_shared(s_x);
        if (tid < 24) cp16(sx + tid * 16, g_x + b * 96 + tid * 4);
        unsigned sh = (unsigned)__cvta_generic_to_shared(s_ht);
        if (tid < 128) cp16(sh + tid * 16, g_h + b * 512 + tid * 4);
        stage_async(W_in, s_W, 512);
        CP_COMMIT(); CP_WAIT0();
    }
    __syncthreads();

    // ---- d2 ----
    for (int p = tid; p < 1024; p += NT) {
        int i = p >> 5, j = p & 31;
        float dx = s_x[i * 3 + 0] - s_x[j * 3 + 0];
        float dy = s_x[i * 3 + 1] - s_x[j * 3 + 1];
        float dz = s_x[i * 3 + 2] - s_x[j * 3 + 2];
        s_d2[p] = dx * dx + dy * dy + dz * dz;
    }
    __syncthreads();

    // ---- adjacency masks + hg = h @ W_in + b_in ----
    #pragma unroll
    for (int rr = 0; rr < 4; rr++) {
        int i = i0 + rr;
        bool adj = (s_d2[i * 32 + lane] < 1.0f) && (lane != i);
        unsigned m = __ballot_sync(0xffffffffu, adj);
        if (lane == 0) s_rmask[i] = m;
    }
    {
        u64 acc[4][2] = {};
        gemmS(s_ht, s_W, i0, k0, acc);
        float4 bb = *(const float4*)&b_in[k0];
        #pragma unroll
        for (int rr = 0; rr < 4; rr++) {
            float4 o = acc4(acc[rr][0], acc[rr][1]);
            o.x += bb.x; o.y += bb.y; o.z += bb.z; o.w += bb.w;
            *(float4*)&s_hg[(i0 + rr) * 128 + k0] = o;
        }
    }
    __syncthreads();

    // ---- edge-list scan (layer-invariant, sorted by i) ----
    if (warp == 0) {
        unsigned m = s_rmask[lane];
        int c = __popc(m);
        int inc = c;
        #pragma unroll
        for (int d = 1; d < 32; d <<= 1) {
            int n = __shfl_up_sync(0xffffffffu, inc, d);
            if (lane >= d) inc += n;
        }
        s_roff[lane] = inc - c;
        if (lane == 31) *s_ne = inc;
    }
    __syncthreads();
    #pragma unroll
    for (int rr = 0; rr < 4; rr++) {
        int i = i0 + rr;
        unsigned m = s_rmask[i];
        if ((m >> lane) & 1u) {
            int pos = s_roff[i] + __popc(m & ((1u << lane) - 1u));
            s_edge[pos] = (i << 5) | lane;
        }
    }
    __syncthreads();
    const int nE = *s_ne;
    const int nper = (nE + 7) >> 3;

    // ---- layers ----
    #pragma unroll 1
    for (int l = 0; l < 2; l++) {
        const float* We1l = We1 + l * (257 * 128);
        const float* We2l = We2 + l * 16384;
        const float* Wh1l = Wh1 + l * (256 * 128);
        const float* Wh2l = Wh2 + l * 16384;

        // mi = hg @ We1a + be1
        stage_async(We1l, s_W, 4096); CP_COMMIT(); CP_WAIT0();
        __syncthreads();
        {
            u64 acc[4][2] = {};
            gemmP(s_hg, 128, s_W, i0, k0, acc);
            float4 bb = *(const float4*)&be1[l * 128 + k0];
            #pragma unroll
            for (int rr = 0; rr < 4; rr++) {
                float4 o = acc4(acc[rr][0], acc[rr][1]);
                o.x += bb.x; o.y += bb.y; o.z += bb.z; o.w += bb.w;
                *(float4*)&s_mi[(i0 + rr) * 128 + k0] = o;
            }
        }
        __syncthreads();

        // mj = hg @ We1b
        stage_async(We1l + 16384, s_W, 4096); CP_COMMIT(); CP_WAIT0();
        __syncthreads();
        {
            u64 acc[4][2] = {};
            gemmP(s_hg, 128, s_W, i0, k0, acc);
            #pragma unroll
            for (int rr = 0; rr < 4; rr++)
                *(float4*)&s_mj[(i0 + rr) * 128 + k0] = acc4(acc[rr][0], acc[rr][1]);
        }
        __syncthreads();

        // stage We2; zero agg
        stage_async(We2l, s_W, 4096); CP_COMMIT();
        for (int v = tid; v < 4096; v += NT) s_agg[v] = 0.0f;
        CP_WAIT0();
        __syncthreads();

        // ---- balanced pair phase: 8 contiguous edge slices ----
        {
            const float4 wdv  = *(const float4*)&We1l[256 * 128 + k0];
            const float4 be2v = *(const float4*)&be2[l * 128 + k0];
            u64* m1d = (u64*)(sm + S_M1) + warp * 512;   // 4 rows x 128 u64
            const int e_lo = min(warp * nper, nE);
            const int e_hi = min(e_lo + nper, nE);

            int   cur_i = -1;
            float a0 = 0.f, a1 = 0.f, a2 = 0.f, a3 = 0.f;

            for (int e0 = e_lo; e0 < e_hi; e0 += 4) {
                // build up to 4 dup'd rows: m1 = silu(mi[i] + mj[j] + d2*wd + be1)
                #pragma unroll
                for (int rr = 0; rr < 4; rr++) {
                    int e = e0 + rr;
                    int ij = s_edge[e < e_hi ? e : (e_hi - 1)];
                    int i = ij >> 5, j = ij & 31;
                    float dd = s_d2[ij];
                    float4 miv = *(const float4*)&s_mi[i * 128 + k0];
                    float4 mjv = *(const float4*)&s_mj[j * 128 + k0];
                    u64 d0  = pk2(silu_f(miv.x + mjv.x + dd * wdv.x));
                    u64 d1  = pk2(silu_f(miv.y + mjv.y + dd * wdv.y));
                    u64 d2v = pk2(silu_f(miv.z + mjv.z + dd * wdv.z));
                    u64 d3  = pk2(silu_f(miv.w + mjv.w + dd * wdv.w));
                    ulonglong2* p = (ulonglong2*)&m1d[rr * 128 + k0];
                    p[0] = make_ulonglong2(d0, d1);
                    p[1] = make_ulonglong2(d2v, d3);
                }
                __syncwarp();
                u64 y[4][2] = {};
                gemmPE(m1d, s_W, k0, y);
                __syncwarp();   // protect m1d before next chunk overwrites

                #pragma unroll
                for (int rr = 0; rr < 4; rr++) {
                    int e = e0 + rr;
                    if (e < e_hi) {
                        int i = s_edge[e] >> 5;   // uniform across warp
                        float4 o = acc4(y[rr][0], y[rr][1]);
                        float v0 = silu_f(o.x + be2v.x);
                        float v1 = silu_f(o.y + be2v.y);
                        float v2 = silu_f(o.z + be2v.z);
                        float v3 = silu_f(o.w + be2v.w);
                        if (i != cur_i) {
                            if (cur_i >= 0) {
                                float* ag = &s_agg[cur_i * 128 + k0];
                                atomicAdd(ag + 0, a0); atomicAdd(ag + 1, a1);
                                atomicAdd(ag + 2, a2); atomicAdd(ag + 3, a3);
                            }
                            cur_i = i;
                            a0 = v0; a1 = v1; a2 = v2; a3 = v3;
                        } else {
                            a0 += v0; a1 += v1; a2 += v2; a3 += v3;
                        }
                    }
                }
            }
            if (cur_i >= 0) {
                float* ag = &s_agg[cur_i * 128 + k0];
                atomicAdd(ag + 0, a0); atomicAdd(ag + 1, a1);
                atomicAdd(ag + 2, a2); atomicAdd(ag + 3, a3);
            }
        }
        __syncthreads();

        // u = silu(hg @ Wh1a + agg @ Wh1b + bh1) -> s_mi
        stage_async(Wh1l, s_W, 4096); CP_COMMIT(); CP_WAIT0();
        __syncthreads();
        u64 acc[4][2] = {};
        gemmP(s_hg, 128, s_W, i0, k0, acc);
        __syncthreads();
        stage_async(Wh1l + 16384, s_W, 4096); CP_COMMIT(); CP_WAIT0();
        __syncthreads();
        gemmP(s_agg, 128, s_W, i0, k0, acc);
        {
            float4 bb = *(const float4*)&bh1[l * 128 + k0];
            #pragma unroll
            for (int rr = 0; rr < 4; rr++) {
                float4 o = acc4(acc[rr][0], acc[rr][1]);
                float4 u4 = { silu_f(o.x + bb.x), silu_f(o.y + bb.y),
                              silu_f(o.z + bb.z), silu_f(o.w + bb.w) };
                *(float4*)&s_mi[(i0 + rr) * 128 + k0] = u4;
            }
        }
        __syncthreads();

        // hg += u @ Wh2 + bh2
        stage_async(Wh2l, s_W, 4096); CP_COMMIT(); CP_WAIT0();
        __syncthreads();
        {
            u64 acc2[4][2] = {};
            gemmP(s_mi, 128, s_W, i0, k0, acc2);
            float4 bb = *(const float4*)&bh2[l * 128 + k0];
            #pragma unroll
            for (int rr = 0; rr < 4; rr++) {
                float4 o = acc4(acc2[rr][0], acc2[rr][1]);
                float4 cur = *(float4*)&s_hg[(i0 + rr) * 128 + k0];
                cur.x += o.x + bb.x; cur.y += o.y + bb.y;
                cur.z += o.z + bb.z; cur.w += o.w + bb.w;
                *(float4*)&s_hg[(i0 + rr) * 128 + k0] = cur;
            }
        }
        __syncthreads();
    }

    // ---- head: ho = hg @ W_out + b_out -> s_mj ----
    stage_async(W_out, s_W, 4096); CP_COMMIT(); CP_WAIT0();
    __syncthreads();
    {
        u64 acc[4][2] = {};
        gemmP(s_hg, 128, s_W, i0, k0, acc);
        float4 bb = *(const float4*)&b_out[k0];
        #pragma unroll
        for (int rr = 0; rr < 4; rr++) {
            float4 o = acc4(acc[rr][0], acc[rr][1]);
            o.x += bb.x; o.y += bb.y; o.z += bb.z; o.w += bb.w;
            *(float4*)&s_mj[(i0 + rr) * 128 + k0] = o;
        }
    }
    __syncthreads();

    // t1 = silu(ho @ Wn1 + bn1) -> s_mi
    stage_async(Wn1, s_W, 4096); CP_COMMIT(); CP_WAIT0();
    __syncthreads();
    {
        u64 acc[4][2] = {};
        gemmP(s_mj, 128, s_W, i0, k0, acc);
        float4 bb = *(const float4*)&bn1[k0];
        #pragma unroll
        for (int rr = 0; rr < 4; rr++) {
            float4 o = acc4(acc[rr][0], acc[rr][1]);
            float4 t = { silu_f(o.x + bb.x), silu_f(o.y + bb.y),
                         silu_f(o.z + bb.z), silu_f(o.w + bb.w) };
            *(float4*)&s_mi[(i0 + rr) * 128 + k0] = t;
        }
    }
    __syncthreads();

    // ---- out[b] = (colsum t1) . Wn2 + 32*bn2 ----
    float part = 0.0f;
    if (tid < 128) {
        float s = 0.0f;
        #pragma unroll
        for (int i = 0; i < 32; i++) s += s_mi[i * 128 + tid];
        part = s * Wn2[tid];
    }
    #pragma unroll
    for (int off = 16; off > 0; off >>= 1)
        part += __shfl_down_sync(0xffffffffu, part, off);
    if (warp < 4 && lane == 0) s_red[warp] = part;
    __syncthreads();
    if (tid == 0)
        g_out[b] = s_red[0] + s_red[1] + s_red[2] + s_red[3] + 32.0f * bn2[0];
}

extern "C" void kernel_launch(void* const* d_in, const int* in_sizes, int n_in,
                              void* d_out, int out_size) {
    const float* g_h   = (const float*)d_in[0];
    const float* g_x   = (const float*)d_in[1];
    const float* W_in  = (const float*)d_in[3];
    const float* b_in  = (const float*)d_in[4];
    const float* We1   = (const float*)d_in[5];
    const float* be1   = (const float*)d_in[6];
    const float* We2   = (const float*)d_in[7];
    const float* be2   = (const float*)d_in[8];
    const float* Wh1   = (const float*)d_in[9];
    const float* bh1   = (const float*)d_in[10];
    const float* Wh2   = (const float*)d_in[11];
    const float* bh2   = (const float*)d_in[12];
    const float* W_out = (const float*)d_in[13];
    const float* b_out = (const float*)d_in[14];
    const float* Wn1   = (const float*)d_in[15];
    const float* bn1   = (const float*)d_in[16];
    const float* Wn2   = (const float*)d_in[17];
    const float* bn2   = (const float*)d_in[18];
    float* out = (float*)d_out;

    const int smem_bytes = SM_FLOATS * 4;
    cudaFuncSetAttribute(sake_kernel, cudaFuncAttributeMaxDynamicSharedMemorySize,
                         smem_bytes);
    sake_kernel<<<NB, NT, smem_bytes>>>(
        g_h, g_x, W_in, b_in, We1, be1, We2, be2, Wh1, bh1, Wh2, bh2,
        W_out, b_out, Wn1, bn1, Wn2, bn2, out);
}